// round 3
// baseline (speedup 1.0000x reference)
#include <cuda_runtime.h>
#include <cuda_bf16.h>
#include <cstdint>

// VQVAE nearest-codebook: bf16 mma.sync (HMMA) fast scores + exact fp32 rescore.
// z: [131072, 64] fp32, codebook: [512, 64] fp32. out = (gather, gather).

#define Dm 64
#define Kc 512
#define ROWS_CTA 256
#define THREADS 512
#define NTILES 64            // 512 codes / 8 per mma tile
#define MARGIN 2e-3f
#define PRUNE_SLACK 5e-4f

__device__ float g_ee[Kc];            // exact sequential ||e_j||^2 (fp32)
__device__ unsigned g_cbw[Kc * 32];   // codebook rows as bf16x2 words

// ---- smem layout (bytes) ----
// zbw  [256*36] u32   bf16x2 of (-2z), pitch 36 words     @ 0      (36864)
// bsw  [512*36] u32   bf16x2 codebook, pitch 36 words     @ 36864  (73728)
// zf   [256*64] f32   exact z rows                        @ 110592 (65536)
// eef  [512]    f32   exact ee                            @ 176128 (2048)
// zzs  [256]    f32   exact zz                            @ 178176 (1024)
// bis  [256]    i32   winning index                       @ 179200 (1024)
#define SM_TOTAL 180224

__global__ void prep_kernel(const float* __restrict__ cb) {
    int j = blockIdx.x * blockDim.x + threadIdx.x;
    if (j < Kc) {
        const float* e = cb + j * Dm;
        float s = 0.0f;
#pragma unroll
        for (int k = 0; k < Dm; ++k) s = __fadd_rn(s, __fmul_rn(e[k], e[k]));
        g_ee[j] = s;
#pragma unroll
        for (int w = 0; w < 32; ++w) {
            __nv_bfloat162 b = __float22bfloat162_rn(make_float2(e[2 * w], e[2 * w + 1]));
            g_cbw[j * 32 + w] = *(unsigned*)&b;
        }
    }
}

__device__ __forceinline__ void mma16816(float& c0, float& c1, float& c2, float& c3,
                                         unsigned a0, unsigned a1, unsigned a2, unsigned a3,
                                         unsigned b0, unsigned b1) {
    asm volatile("mma.sync.aligned.m16n8k16.row.col.f32.bf16.bf16.f32 "
                 "{%0,%1,%2,%3},{%4,%5,%6,%7},{%8,%9},{%0,%1,%2,%3};"
                 : "+f"(c0), "+f"(c1), "+f"(c2), "+f"(c3)
                 : "r"(a0), "r"(a1), "r"(a2), "r"(a3), "r"(b0), "r"(b1));
}

__device__ __forceinline__ void rescore(const float* __restrict__ zr, float zz, int j,
                                        const float* __restrict__ cb,
                                        const float* __restrict__ eef,
                                        float& bv, int& bi) {
    const float* e = cb + (size_t)j * Dm;
    float dot = 0.0f;
#pragma unroll
    for (int k = 0; k < Dm; ++k) dot = __fmaf_rn(zr[k], __ldg(e + k), dot);
    float sx = __fadd_rn(__fadd_rn(zz, eef[j]), __fmul_rn(-2.0f, dot));
    if (sx < bv || (sx == bv && j < bi)) { bv = sx; bi = j; }
}

__global__ void __launch_bounds__(THREADS, 1)
vq_kernel(const float* __restrict__ z, const float* __restrict__ cb,
          float* __restrict__ out, long long half) {
    extern __shared__ char sm[];
    unsigned* zbw = (unsigned*)(sm);
    unsigned* bsw = (unsigned*)(sm + 36864);
    float* zf = (float*)(sm + 110592);
    float* eef = (float*)(sm + 176128);
    float* zzs = (float*)(sm + 178176);
    int* bis = (int*)(sm + 179200);

    const int tid = threadIdx.x, lane = tid & 31, wid = tid >> 5;
    const int q = lane & 3, rg = lane >> 2;

    // ---------------- prolog ----------------
    if (tid < ROWS_CTA) {
        const float4* zr = (const float4*)(z + ((size_t)blockIdx.x * ROWS_CTA + tid) * Dm);
        float4 v[16];
#pragma unroll
        for (int i = 0; i < 16; ++i) v[i] = zr[i];
        float4* zd = (float4*)(zf + tid * Dm);
#pragma unroll
        for (int i = 0; i < 16; ++i) zd[i] = v[i];
        float zz = 0.0f;
#pragma unroll
        for (int i = 0; i < 16; ++i) {
            zz = __fadd_rn(zz, __fmul_rn(v[i].x, v[i].x));
            zz = __fadd_rn(zz, __fmul_rn(v[i].y, v[i].y));
            zz = __fadd_rn(zz, __fmul_rn(v[i].z, v[i].z));
            zz = __fadd_rn(zz, __fmul_rn(v[i].w, v[i].w));
        }
        zzs[tid] = zz;
        unsigned* zrow = zbw + tid * 36;
#pragma unroll
        for (int i = 0; i < 16; ++i) {
            __nv_bfloat162 b0 = __float22bfloat162_rn(make_float2(-2.f * v[i].x, -2.f * v[i].y));
            __nv_bfloat162 b1 = __float22bfloat162_rn(make_float2(-2.f * v[i].z, -2.f * v[i].w));
            zrow[2 * i] = *(unsigned*)&b0;
            zrow[2 * i + 1] = *(unsigned*)&b1;
        }
    } else {
        int t2 = tid - ROWS_CTA;       // 0..255: copies 2 codebook rows + ee
#pragma unroll
        for (int rr = 0; rr < 2; ++rr) {
            int j = t2 * 2 + rr;
            const uint4* src = (const uint4*)(g_cbw + j * 32);
            uint4* dst = (uint4*)(bsw + j * 36);   // 144B row pitch: 16B aligned
#pragma unroll
            for (int i = 0; i < 8; ++i) dst[i] = src[i];
            eef[j] = g_ee[j];
        }
    }
    __syncthreads();

    // ---------------- A fragments (fixed over tiles) ----------------
    const int warpRow = wid * 16;
    const int ra = warpRow + rg;
    unsigned a[16];
#pragma unroll
    for (int ks = 0; ks < 4; ++ks) {
        a[ks * 4 + 0] = zbw[ra * 36 + q + ks * 8];
        a[ks * 4 + 1] = zbw[(ra + 8) * 36 + q + ks * 8];
        a[ks * 4 + 2] = zbw[ra * 36 + q + 4 + ks * 8];
        a[ks * 4 + 3] = zbw[(ra + 8) * 36 + q + 4 + ks * 8];
    }

    const float2* ee2p = (const float2*)eef;

    // ---------------- pass 1: fast min per row + per-tile mins ----------------
    float mr0 = 1e30f, mr1 = 1e30f;
    unsigned tmins[NTILES / 2];
    unsigned tmplo = 0;
#pragma unroll
    for (int t = 0; t < NTILES; ++t) {
        float2 e2 = ee2p[t * 4 + q];
        float c0 = e2.x, c1 = e2.y, c2 = e2.x, c3 = e2.y;
        int bw = (t * 8 + rg) * 36 + q;
#pragma unroll
        for (int ks = 0; ks < 4; ++ks)
            mma16816(c0, c1, c2, c3, a[ks * 4], a[ks * 4 + 1], a[ks * 4 + 2], a[ks * 4 + 3],
                     bsw[bw + ks * 8], bsw[bw + 4 + ks * 8]);
        float m01 = fminf(c0, c1), m23 = fminf(c2, c3);
        mr0 = fminf(mr0, m01);
        mr1 = fminf(mr1, m23);
        unsigned short h = __bfloat16_as_ushort(__float2bfloat16(fminf(m01, m23)));
        if (t & 1) tmins[t >> 1] = tmplo | ((unsigned)h << 16);
        else       tmplo = (unsigned)h;
    }

#pragma unroll
    for (int off = 1; off < 4; off <<= 1) {
        mr0 = fminf(mr0, __shfl_xor_sync(0xffffffffu, mr0, off));
        mr1 = fminf(mr1, __shfl_xor_sync(0xffffffffu, mr1, off));
    }
    const float thr0 = mr0 + MARGIN, thr1 = mr1 + MARGIN;
    const float thrp = fmaxf(thr0, thr1) + PRUNE_SLACK;

    // ---------------- pass 2: pruned recompute + exact rescore ----------------
    float bv0 = 1e30f, bv1 = 1e30f;
    int bi0 = 0x7fffffff, bi1 = 0x7fffffff;
    const float* zr0 = zf + (size_t)ra * Dm;
    const float* zr1 = zr0 + 8 * Dm;
    const float zz0 = zzs[ra], zz1 = zzs[ra + 8];

#pragma unroll
    for (int t = 0; t < NTILES; ++t) {
        unsigned w = tmins[t >> 1];
        unsigned short h = (t & 1) ? (unsigned short)(w >> 16) : (unsigned short)(w & 0xffff);
        float tm = __bfloat162float(__ushort_as_bfloat16(h));
        if (!__any_sync(0xffffffffu, tm <= thrp)) continue;

        float2 e2 = ee2p[t * 4 + q];
        float c0 = e2.x, c1 = e2.y, c2 = e2.x, c3 = e2.y;
        int bw = (t * 8 + rg) * 36 + q;
#pragma unroll
        for (int ks = 0; ks < 4; ++ks)
            mma16816(c0, c1, c2, c3, a[ks * 4], a[ks * 4 + 1], a[ks * 4 + 2], a[ks * 4 + 3],
                     bsw[bw + ks * 8], bsw[bw + 4 + ks * 8]);

        int jb = t * 8 + 2 * q;
        if (c0 <= thr0) rescore(zr0, zz0, jb,     cb, eef, bv0, bi0);
        if (c1 <= thr0) rescore(zr0, zz0, jb + 1, cb, eef, bv0, bi0);
        if (c2 <= thr1) rescore(zr1, zz1, jb,     cb, eef, bv1, bi1);
        if (c3 <= thr1) rescore(zr1, zz1, jb + 1, cb, eef, bv1, bi1);
    }

    // quad reduce (value, index) with first-index tie-break
#pragma unroll
    for (int off = 1; off < 4; off <<= 1) {
        float ov = __shfl_xor_sync(0xffffffffu, bv0, off);
        int oi = __shfl_xor_sync(0xffffffffu, bi0, off);
        if (ov < bv0 || (ov == bv0 && oi < bi0)) { bv0 = ov; bi0 = oi; }
        ov = __shfl_xor_sync(0xffffffffu, bv1, off);
        oi = __shfl_xor_sync(0xffffffffu, bi1, off);
        if (ov < bv1 || (ov == bv1 && oi < bi1)) { bv1 = ov; bi1 = oi; }
    }
    if (q == 0) {
        bis[ra] = bi0;
        bis[ra + 8] = bi1;
    }
    __syncthreads();

    // ---------------- gather + write both tuple halves ----------------
    {
        int row = tid >> 1, hh = tid & 1;
        int j = bis[row];
        size_t g = (size_t)blockIdx.x * ROWS_CTA + row;
        const float4* s4 = (const float4*)(cb + (size_t)j * Dm + hh * 32);
        float4* o1 = (float4*)(out + g * Dm + hh * 32);
        float4* o2 = (half > 0) ? (float4*)(out + half + g * Dm + hh * 32) : nullptr;
#pragma unroll
        for (int i = 0; i < 8; ++i) {
            float4 tv = s4[i];
            o1[i] = tv;
            if (o2) o2[i] = tv;
        }
    }
}

extern "C" void kernel_launch(void* const* d_in, const int* in_sizes, int n_in,
                              void* d_out, int out_size) {
    const float* z = (const float*)d_in[0];
    const float* cb = (const float*)d_in[1];
    float* out = (float*)d_out;
    const int N = in_sizes[0] / Dm;                      // 131072
    long long half = ((long long)out_size >= 2LL * N * Dm) ? (long long)out_size / 2 : 0;

    cudaFuncSetAttribute(vq_kernel, cudaFuncAttributeMaxDynamicSharedMemorySize, SM_TOTAL);
    prep_kernel<<<2, 256>>>(cb);
    vq_kernel<<<N / ROWS_CTA, THREADS, SM_TOTAL>>>(z, cb, out, half);
}

// round 4
// speedup vs baseline: 4.5086x; 4.5086x over previous
#include <cuda_runtime.h>
#include <cuda_bf16.h>
#include <cuda_fp16.h>
#include <cstdint>

// VQVAE nearest-codebook: bf16 mma.sync fast scores + exact fp32 rescore.
// z: [131072, 64] fp32, codebook: [512, 64] fp32. out = (gather, gather).

#define Dm 64
#define Kc 512
#define ROWS_CTA 512
#define THREADS 512
#define NTILES 64
#define MARGIN 2e-3f
#define PRUNE_SLACK 5e-4f

__device__ float g_ee[Kc];            // exact sequential ||e_j||^2
__device__ unsigned g_cbw[Kc * 32];   // codebook rows as bf16x2 words

// ---- smem layout (bytes) ----
#define SM_ZBW  0                      // 512 x 36 u32 (bf16x2 of -2z, pitch 36)   73728
#define SM_BSW  73728                  // 512 x 36 u32 (bf16x2 codebook)           73728
#define SM_TMIN 147456                 // 16 warps x 64 tiles x 8 quads, fp16      16384
#define SM_EEF  163840                 // 512 f32 exact ee                          2048
#define SM_ZZS  165888                 // 512 f32 exact zz                          2048
#define SM_BIS  167936                 // 512 i32 winner                            2048
#define SM_TOTAL 169984

__global__ void prep_kernel(const float* __restrict__ cb) {
    int j = blockIdx.x * blockDim.x + threadIdx.x;
    if (j < Kc) {
        const float* e = cb + j * Dm;
        float s = 0.0f;
#pragma unroll
        for (int k = 0; k < Dm; ++k) s = __fadd_rn(s, __fmul_rn(e[k], e[k]));
        g_ee[j] = s;
#pragma unroll
        for (int w = 0; w < 32; ++w) {
            __nv_bfloat162 b = __float22bfloat162_rn(make_float2(e[2 * w], e[2 * w + 1]));
            g_cbw[j * 32 + w] = *(unsigned*)&b;
        }
    }
}

__device__ __forceinline__ void mma16816(float& c0, float& c1, float& c2, float& c3,
                                         unsigned a0, unsigned a1, unsigned a2, unsigned a3,
                                         unsigned b0, unsigned b1) {
    asm volatile("mma.sync.aligned.m16n8k16.row.col.f32.bf16.bf16.f32 "
                 "{%0,%1,%2,%3},{%4,%5,%6,%7},{%8,%9},{%0,%1,%2,%3};"
                 : "+f"(c0), "+f"(c1), "+f"(c2), "+f"(c3)
                 : "r"(a0), "r"(a1), "r"(a2), "r"(a3), "r"(b0), "r"(b1));
}

// ONE copy of the exact-rescore code (noinline: code-size control).
__device__ __noinline__ void rescore(const float* __restrict__ zr, float zz, int j,
                                     const float* __restrict__ cb,
                                     const float* __restrict__ eef,
                                     float& bv, int& bi) {
    const float* e = cb + (size_t)j * Dm;
    float dot = 0.0f;
#pragma unroll 8
    for (int k = 0; k < Dm; ++k) dot = __fmaf_rn(__ldg(zr + k), __ldg(e + k), dot);
    float sx = __fadd_rn(__fadd_rn(zz, eef[j]), __fmul_rn(-2.0f, dot));
    if (sx < bv || (sx == bv && j < bi)) { bv = sx; bi = j; }
}

__global__ void __launch_bounds__(THREADS, 1)
vq_kernel(const float* __restrict__ z, const float* __restrict__ cb,
          float* __restrict__ out, long long half) {
    extern __shared__ char sm[];
    unsigned* zbw = (unsigned*)(sm + SM_ZBW);
    unsigned* bsw = (unsigned*)(sm + SM_BSW);
    __half* tminp = (__half*)(sm + SM_TMIN);
    float* eef = (float*)(sm + SM_EEF);
    float* zzs = (float*)(sm + SM_ZZS);
    int* bis = (int*)(sm + SM_BIS);

    const int tid = threadIdx.x, lane = tid & 31, wid = tid >> 5;
    const int q = lane & 3, rg = lane >> 2;
    const size_t blockRow = (size_t)blockIdx.x * ROWS_CTA;

    // ---------------- prolog ----------------
    {   // z row -> exact zz + bf16(-2z) staged (pitch 36)
        const float4* zr = (const float4*)(z + (blockRow + tid) * Dm);
        float4 v[16];
#pragma unroll
        for (int i = 0; i < 16; ++i) v[i] = zr[i];
        float zz = 0.0f;
#pragma unroll
        for (int i = 0; i < 16; ++i) {
            zz = __fadd_rn(zz, __fmul_rn(v[i].x, v[i].x));
            zz = __fadd_rn(zz, __fmul_rn(v[i].y, v[i].y));
            zz = __fadd_rn(zz, __fmul_rn(v[i].z, v[i].z));
            zz = __fadd_rn(zz, __fmul_rn(v[i].w, v[i].w));
        }
        zzs[tid] = zz;
        unsigned p[32];
#pragma unroll
        for (int i = 0; i < 16; ++i) {
            __nv_bfloat162 b0 = __float22bfloat162_rn(make_float2(-2.f * v[i].x, -2.f * v[i].y));
            __nv_bfloat162 b1 = __float22bfloat162_rn(make_float2(-2.f * v[i].z, -2.f * v[i].w));
            p[2 * i] = *(unsigned*)&b0;
            p[2 * i + 1] = *(unsigned*)&b1;
        }
        uint4* d4 = (uint4*)(zbw + tid * 36);
#pragma unroll
        for (int i = 0; i < 8; ++i) d4[i] = make_uint4(p[4 * i], p[4 * i + 1], p[4 * i + 2], p[4 * i + 3]);
    }
    // codebook bf16 words -> pitch-36 smem (coalesced LDG, conflict-free STS)
#pragma unroll 4
    for (int u = tid; u < Kc * 32; u += THREADS) {
        int r = u >> 5, w = u & 31;
        bsw[r * 36 + w] = g_cbw[u];
    }
    if (tid < Kc) eef[tid] = g_ee[tid];
    __syncthreads();

    // ---------------- A fragments: 2 row-blocks of 16, M=32 per warp ----------------
    const int warpRow = wid * 32;
    const int ra = warpRow + rg;     // rows ra, ra+8 (block0), ra+16, ra+24 (block1)
    unsigned a[32];
#pragma unroll
    for (int b = 0; b < 2; ++b)
#pragma unroll
        for (int ks = 0; ks < 4; ++ks) {
            int rbase = (ra + 16 * b) * 36;
            a[b * 16 + ks * 4 + 0] = zbw[rbase + q + ks * 8];
            a[b * 16 + ks * 4 + 1] = zbw[rbase + 8 * 36 + q + ks * 8];
            a[b * 16 + ks * 4 + 2] = zbw[rbase + q + 4 + ks * 8];
            a[b * 16 + ks * 4 + 3] = zbw[rbase + 8 * 36 + q + 4 + ks * 8];
        }
    const float2* ee2p = (const float2*)eef;

    // ---------------- pass 1: fast min per row + per-(tile,quad) min ----------------
    float mr0 = 1e30f, mr1 = 1e30f, mr2 = 1e30f, mr3 = 1e30f;
#pragma unroll 2
    for (int t = 0; t < NTILES; ++t) {
        float2 e2 = ee2p[t * 4 + q];
        float c0 = e2.x, c1 = e2.y, c2 = e2.x, c3 = e2.y;
        float c4 = e2.x, c5 = e2.y, c6 = e2.x, c7 = e2.y;
        int bw = (t * 8 + rg) * 36 + q;
#pragma unroll
        for (int ks = 0; ks < 4; ++ks) {
            unsigned b0 = bsw[bw + ks * 8], b1 = bsw[bw + 4 + ks * 8];
            mma16816(c0, c1, c2, c3, a[ks * 4], a[ks * 4 + 1], a[ks * 4 + 2], a[ks * 4 + 3], b0, b1);
            mma16816(c4, c5, c6, c7, a[16 + ks * 4], a[17 + ks * 4], a[18 + ks * 4], a[19 + ks * 4], b0, b1);
        }
        mr0 = fminf(mr0, fminf(c0, c1));
        mr1 = fminf(mr1, fminf(c2, c3));
        mr2 = fminf(mr2, fminf(c4, c5));
        mr3 = fminf(mr3, fminf(c6, c7));
        float tm = fminf(fminf(fminf(c0, c1), fminf(c2, c3)),
                         fminf(fminf(c4, c5), fminf(c6, c7)));
        tm = fminf(tm, __shfl_xor_sync(0xffffffffu, tm, 1));
        tm = fminf(tm, __shfl_xor_sync(0xffffffffu, tm, 2));
        if (q == 0) tminp[(wid * NTILES + t) * 8 + rg] = __float2half(tm);
    }
    __syncwarp();

#pragma unroll
    for (int off = 1; off < 4; off <<= 1) {
        mr0 = fminf(mr0, __shfl_xor_sync(0xffffffffu, mr0, off));
        mr1 = fminf(mr1, __shfl_xor_sync(0xffffffffu, mr1, off));
        mr2 = fminf(mr2, __shfl_xor_sync(0xffffffffu, mr2, off));
        mr3 = fminf(mr3, __shfl_xor_sync(0xffffffffu, mr3, off));
    }
    const float t0 = mr0 + MARGIN, t1 = mr1 + MARGIN, t2 = mr2 + MARGIN, t3 = mr3 + MARGIN;
    const float thrq = fmaxf(fmaxf(t0, t1), fmaxf(t2, t3)) + PRUNE_SLACK;

    // ---------------- pass 2: pruned recompute + exact rescore ----------------
    float bv0 = 1e30f, bv1 = 1e30f, bv2 = 1e30f, bv3 = 1e30f;
    int bi0 = 0x7fffffff, bi1 = 0x7fffffff, bi2 = 0x7fffffff, bi3 = 0x7fffffff;
    const float* zr0 = z + (blockRow + ra) * Dm;
    const float zz0 = zzs[ra], zz1 = zzs[ra + 8], zz2 = zzs[ra + 16], zz3 = zzs[ra + 24];

#pragma unroll 1
    for (int t = 0; t < NTILES; ++t) {
        float tm = __half2float(tminp[(wid * NTILES + t) * 8 + rg]);
        if (!__any_sync(0xffffffffu, tm <= thrq)) continue;

        float2 e2 = ee2p[t * 4 + q];
        float c0 = e2.x, c1 = e2.y, c2 = e2.x, c3 = e2.y;
        float c4 = e2.x, c5 = e2.y, c6 = e2.x, c7 = e2.y;
        int bw = (t * 8 + rg) * 36 + q;
#pragma unroll
        for (int ks = 0; ks < 4; ++ks) {
            unsigned b0 = bsw[bw + ks * 8], b1 = bsw[bw + 4 + ks * 8];
            mma16816(c0, c1, c2, c3, a[ks * 4], a[ks * 4 + 1], a[ks * 4 + 2], a[ks * 4 + 3], b0, b1);
            mma16816(c4, c5, c6, c7, a[16 + ks * 4], a[17 + ks * 4], a[18 + ks * 4], a[19 + ks * 4], b0, b1);
        }
        int jb = t * 8 + 2 * q;
        if (c0 <= t0) rescore(zr0, zz0, jb,     cb, eef, bv0, bi0);
        if (c1 <= t0) rescore(zr0, zz0, jb + 1, cb, eef, bv0, bi0);
        if (c2 <= t1) rescore(zr0 + 8 * Dm,  zz1, jb,     cb, eef, bv1, bi1);
        if (c3 <= t1) rescore(zr0 + 8 * Dm,  zz1, jb + 1, cb, eef, bv1, bi1);
        if (c4 <= t2) rescore(zr0 + 16 * Dm, zz2, jb,     cb, eef, bv2, bi2);
        if (c5 <= t2) rescore(zr0 + 16 * Dm, zz2, jb + 1, cb, eef, bv2, bi2);
        if (c6 <= t3) rescore(zr0 + 24 * Dm, zz3, jb,     cb, eef, bv3, bi3);
        if (c7 <= t3) rescore(zr0 + 24 * Dm, zz3, jb + 1, cb, eef, bv3, bi3);
    }

    // quad reduce (value, first-index) and publish
#pragma unroll
    for (int off = 1; off < 4; off <<= 1) {
        float ov; int oi;
        ov = __shfl_xor_sync(0xffffffffu, bv0, off); oi = __shfl_xor_sync(0xffffffffu, bi0, off);
        if (ov < bv0 || (ov == bv0 && oi < bi0)) { bv0 = ov; bi0 = oi; }
        ov = __shfl_xor_sync(0xffffffffu, bv1, off); oi = __shfl_xor_sync(0xffffffffu, bi1, off);
        if (ov < bv1 || (ov == bv1 && oi < bi1)) { bv1 = ov; bi1 = oi; }
        ov = __shfl_xor_sync(0xffffffffu, bv2, off); oi = __shfl_xor_sync(0xffffffffu, bi2, off);
        if (ov < bv2 || (ov == bv2 && oi < bi2)) { bv2 = ov; bi2 = oi; }
        ov = __shfl_xor_sync(0xffffffffu, bv3, off); oi = __shfl_xor_sync(0xffffffffu, bi3, off);
        if (ov < bv3 || (ov == bv3 && oi < bi3)) { bv3 = ov; bi3 = oi; }
    }
    if (q == 0) {
        bis[ra] = bi0; bis[ra + 8] = bi1; bis[ra + 16] = bi2; bis[ra + 24] = bi3;
    }
    __syncthreads();

    // ---------------- gather + write both tuple halves ----------------
#pragma unroll
    for (int it = 0; it < 2; ++it) {
        int row = (tid >> 1) + it * 256, hh = tid & 1;
        int j = bis[row];
        size_t g = blockRow + row;
        const float4* s4 = (const float4*)(cb + (size_t)j * Dm + hh * 32);
        float4* o1 = (float4*)(out + g * Dm + hh * 32);
        float4* o2 = (half > 0) ? (float4*)(out + half + g * Dm + hh * 32) : nullptr;
#pragma unroll
        for (int i = 0; i < 8; ++i) {
            float4 tv = s4[i];
            o1[i] = tv;
            if (o2) o2[i] = tv;
        }
    }
}

extern "C" void kernel_launch(void* const* d_in, const int* in_sizes, int n_in,
                              void* d_out, int out_size) {
    const float* z = (const float*)d_in[0];
    const float* cb = (const float*)d_in[1];
    float* out = (float*)d_out;
    const int N = in_sizes[0] / Dm;                      // 131072
    long long half = ((long long)out_size >= 2LL * N * Dm) ? (long long)out_size / 2 : 0;

    cudaFuncSetAttribute(vq_kernel, cudaFuncAttributeMaxDynamicSharedMemorySize, SM_TOTAL);
    prep_kernel<<<2, 256>>>(cb);
    vq_kernel<<<N / ROWS_CTA, THREADS, SM_TOTAL>>>(z, cb, out, half);
}

// round 5
// speedup vs baseline: 9.0394x; 2.0049x over previous
#include <cuda_runtime.h>
#include <cuda_bf16.h>
#include <cuda_fp16.h>
#include <cstdint>

// VQVAE nearest-codebook: bf16 mma.sync fast scores + warp-parallel exact fp32 rescore.
// z: [131072, 64] fp32, codebook: [512, 64] fp32. out = (gather, gather).

#define Dm 64
#define Kc 512
#define ROWS_CTA 512
#define THREADS 512
#define NTILES 64
#define MARGIN 2e-3f
#define PRUNE_SLACK 5e-4f
#define QCAP 256

__device__ float g_ee[Kc];            // exact sequential ||e_j||^2
__device__ unsigned g_cbw[Kc * 32];   // codebook rows as bf16x2 words

// ---- smem layout (bytes) ----
#define SM_ZBW  0                      // 512 x 36 u32 bf16x2(-2z), pitch 36      73728
#define SM_BSW  73728                  // 512 x 36 u32 bf16x2 codebook            73728
#define SM_TMIN 147456                 // 16 warps x 64 tiles x 8 rg, fp16        16384
#define SM_EEF  163840                 // 512 f32 exact ee                         2048
#define SM_ZZS  165888                 // 512 f32 exact zz                         2048
#define SM_MINR 167936                 // 512 u64 (score_bits<<32 | j)             4096
#define SM_QCNT 172032                 // 16 i32 (padded 128)                       128
#define SM_QUE  172160                 // 16 x 256 u32 candidates                 16384
#define SM_TOTAL 188544

__global__ void prep_kernel(const float* __restrict__ cb) {
    int j = blockIdx.x * blockDim.x + threadIdx.x;
    if (j < Kc) {
        const float* e = cb + j * Dm;
        float s = 0.0f;
#pragma unroll
        for (int k = 0; k < Dm; ++k) s = __fadd_rn(s, __fmul_rn(e[k], e[k]));
        g_ee[j] = s;
#pragma unroll
        for (int w = 0; w < 32; ++w) {
            __nv_bfloat162 b = __float22bfloat162_rn(make_float2(e[2 * w], e[2 * w + 1]));
            g_cbw[j * 32 + w] = *(unsigned*)&b;
        }
    }
}

__device__ __forceinline__ void mma16816(float& c0, float& c1, float& c2, float& c3,
                                         unsigned a0, unsigned a1, unsigned a2, unsigned a3,
                                         unsigned b0, unsigned b1) {
    asm volatile("mma.sync.aligned.m16n8k16.row.col.f32.bf16.bf16.f32 "
                 "{%0,%1,%2,%3},{%4,%5,%6,%7},{%8,%9},{%0,%1,%2,%3};"
                 : "+f"(c0), "+f"(c1), "+f"(c2), "+f"(c3)
                 : "r"(a0), "r"(a1), "r"(a2), "r"(a3), "r"(b0), "r"(b1));
}

// Exact rescore (sequential fp32, matches reference rounding) + commit via
// 64-bit atomicMin key: (score_bits<<32)|j. Scores ~64 > 0, so float-bit
// ordering == value ordering; ties resolve to smallest j (first-index).
__device__ __noinline__ void exact_commit(unsigned pk, const float* __restrict__ z,
                                          const float* __restrict__ cb, size_t blockRow,
                                          const float* zzs, const float* eef,
                                          unsigned long long* minr) {
    int row = pk & 511;
    int j = pk >> 9;
    const float4* zp = (const float4*)(z + (blockRow + row) * Dm);
    const float4* ep = (const float4*)(cb + (size_t)j * Dm);
    float dot = 0.0f;
#pragma unroll
    for (int i = 0; i < 16; ++i) {
        float4 a = __ldg(zp + i);
        float4 b = __ldg(ep + i);
        dot = __fmaf_rn(a.x, b.x, dot);
        dot = __fmaf_rn(a.y, b.y, dot);
        dot = __fmaf_rn(a.z, b.z, dot);
        dot = __fmaf_rn(a.w, b.w, dot);
    }
    float sx = __fadd_rn(__fadd_rn(zzs[row], eef[j]), __fmul_rn(-2.0f, dot));
    unsigned long long key = ((unsigned long long)__float_as_uint(sx) << 32) | (unsigned)j;
    atomicMin(minr + row, key);
}

__global__ void __launch_bounds__(THREADS, 1)
vq_kernel(const float* __restrict__ z, const float* __restrict__ cb,
          float* __restrict__ out, long long half) {
    extern __shared__ char sm[];
    unsigned* zbw = (unsigned*)(sm + SM_ZBW);
    unsigned* bsw = (unsigned*)(sm + SM_BSW);
    __half* tminp = (__half*)(sm + SM_TMIN);
    float* eef = (float*)(sm + SM_EEF);
    float* zzs = (float*)(sm + SM_ZZS);
    unsigned long long* minr = (unsigned long long*)(sm + SM_MINR);
    int* qcnt = (int*)(sm + SM_QCNT);
    unsigned* que = (unsigned*)(sm + SM_QUE);

    const int tid = threadIdx.x, lane = tid & 31, wid = tid >> 5;
    const int q = lane & 3, rg = lane >> 2;
    const size_t blockRow = (size_t)blockIdx.x * ROWS_CTA;

    minr[tid] = ~0ull;
    if (tid < 16) qcnt[tid] = 0;

    // ---------------- prolog ----------------
    {   // z row -> exact zz + bf16(-2z) staged (pitch 36)
        const float4* zr = (const float4*)(z + (blockRow + tid) * Dm);
        float4 v[16];
#pragma unroll
        for (int i = 0; i < 16; ++i) v[i] = zr[i];
        float zz = 0.0f;
#pragma unroll
        for (int i = 0; i < 16; ++i) {
            zz = __fadd_rn(zz, __fmul_rn(v[i].x, v[i].x));
            zz = __fadd_rn(zz, __fmul_rn(v[i].y, v[i].y));
            zz = __fadd_rn(zz, __fmul_rn(v[i].z, v[i].z));
            zz = __fadd_rn(zz, __fmul_rn(v[i].w, v[i].w));
        }
        zzs[tid] = zz;
        unsigned p[32];
#pragma unroll
        for (int i = 0; i < 16; ++i) {
            __nv_bfloat162 b0 = __float22bfloat162_rn(make_float2(-2.f * v[i].x, -2.f * v[i].y));
            __nv_bfloat162 b1 = __float22bfloat162_rn(make_float2(-2.f * v[i].z, -2.f * v[i].w));
            p[2 * i] = *(unsigned*)&b0;
            p[2 * i + 1] = *(unsigned*)&b1;
        }
        uint4* d4 = (uint4*)(zbw + tid * 36);
#pragma unroll
        for (int i = 0; i < 8; ++i) d4[i] = make_uint4(p[4 * i], p[4 * i + 1], p[4 * i + 2], p[4 * i + 3]);
    }
    // codebook bf16 words -> pitch-36 smem (vectorized)
    {
        const uint4* src = (const uint4*)g_cbw;
#pragma unroll
        for (int it = 0; it < 8; ++it) {
            int u = tid + it * THREADS;          // 0..4095 uint4 chunks
            int r = u >> 3, c4 = u & 7;
            *(uint4*)(bsw + r * 36 + c4 * 4) = src[u];
        }
    }
    if (tid < Kc) eef[tid] = g_ee[tid];
    __syncthreads();

    // ---------------- A fragments: M=32 per warp ----------------
    const int warpRow = wid * 32;
    const int ra = warpRow + rg;
    unsigned a[32];
#pragma unroll
    for (int b = 0; b < 2; ++b)
#pragma unroll
        for (int ks = 0; ks < 4; ++ks) {
            int rbase = (ra + 16 * b) * 36;
            a[b * 16 + ks * 4 + 0] = zbw[rbase + q + ks * 8];
            a[b * 16 + ks * 4 + 1] = zbw[rbase + 8 * 36 + q + ks * 8];
            a[b * 16 + ks * 4 + 2] = zbw[rbase + q + 4 + ks * 8];
            a[b * 16 + ks * 4 + 3] = zbw[rbase + 8 * 36 + q + 4 + ks * 8];
        }
    const float2* ee2p = (const float2*)eef;

    // ---------------- pass 1: fast mins ----------------
    float mr0 = 1e30f, mr1 = 1e30f, mr2 = 1e30f, mr3 = 1e30f;
#pragma unroll 2
    for (int t = 0; t < NTILES; ++t) {
        float2 e2 = ee2p[t * 4 + q];
        float c0 = e2.x, c1 = e2.y, c2 = e2.x, c3 = e2.y;
        float c4 = e2.x, c5 = e2.y, c6 = e2.x, c7 = e2.y;
        int bw = (t * 8 + rg) * 36 + q;
#pragma unroll
        for (int ks = 0; ks < 4; ++ks) {
            unsigned b0 = bsw[bw + ks * 8], b1 = bsw[bw + 4 + ks * 8];
            mma16816(c0, c1, c2, c3, a[ks * 4], a[ks * 4 + 1], a[ks * 4 + 2], a[ks * 4 + 3], b0, b1);
            mma16816(c4, c5, c6, c7, a[16 + ks * 4], a[17 + ks * 4], a[18 + ks * 4], a[19 + ks * 4], b0, b1);
        }
        mr0 = fminf(mr0, fminf(c0, c1));
        mr1 = fminf(mr1, fminf(c2, c3));
        mr2 = fminf(mr2, fminf(c4, c5));
        mr3 = fminf(mr3, fminf(c6, c7));
        float tm = fminf(fminf(fminf(c0, c1), fminf(c2, c3)),
                         fminf(fminf(c4, c5), fminf(c6, c7)));
        tm = fminf(tm, __shfl_xor_sync(0xffffffffu, tm, 1));
        tm = fminf(tm, __shfl_xor_sync(0xffffffffu, tm, 2));
        if (q == 0) tminp[(wid * NTILES + t) * 8 + rg] = __float2half(tm);
    }
    __syncwarp();

#pragma unroll
    for (int off = 1; off < 4; off <<= 1) {
        mr0 = fminf(mr0, __shfl_xor_sync(0xffffffffu, mr0, off));
        mr1 = fminf(mr1, __shfl_xor_sync(0xffffffffu, mr1, off));
        mr2 = fminf(mr2, __shfl_xor_sync(0xffffffffu, mr2, off));
        mr3 = fminf(mr3, __shfl_xor_sync(0xffffffffu, mr3, off));
    }
    const float t0 = mr0 + MARGIN, t1 = mr1 + MARGIN, t2 = mr2 + MARGIN, t3 = mr3 + MARGIN;
    const float thrq = fmaxf(fmaxf(t0, t1), fmaxf(t2, t3)) + PRUNE_SLACK;

    // ---------------- pass 2: pruned recompute, enqueue candidates ----------------
#define PUSH(rowv, jv) do {                                                       \
        unsigned pk_ = (unsigned)(rowv) | ((unsigned)(jv) << 9);                  \
        int qi_ = atomicAdd(qcnt + wid, 1);                                       \
        if (qi_ < QCAP) que[wid * QCAP + qi_] = pk_;                              \
        else exact_commit(pk_, z, cb, blockRow, zzs, eef, minr);                  \
    } while (0)

#pragma unroll 1
    for (int t = 0; t < NTILES; ++t) {
        float tm = __half2float(tminp[(wid * NTILES + t) * 8 + rg]);
        if (!__any_sync(0xffffffffu, tm <= thrq)) continue;

        float2 e2 = ee2p[t * 4 + q];
        float c0 = e2.x, c1 = e2.y, c2 = e2.x, c3 = e2.y;
        float c4 = e2.x, c5 = e2.y, c6 = e2.x, c7 = e2.y;
        int bw = (t * 8 + rg) * 36 + q;
#pragma unroll
        for (int ks = 0; ks < 4; ++ks) {
            unsigned b0 = bsw[bw + ks * 8], b1 = bsw[bw + 4 + ks * 8];
            mma16816(c0, c1, c2, c3, a[ks * 4], a[ks * 4 + 1], a[ks * 4 + 2], a[ks * 4 + 3], b0, b1);
            mma16816(c4, c5, c6, c7, a[16 + ks * 4], a[17 + ks * 4], a[18 + ks * 4], a[19 + ks * 4], b0, b1);
        }
        int jb = t * 8 + 2 * q;
        if (c0 <= t0) PUSH(ra, jb);
        if (c1 <= t0) PUSH(ra, jb + 1);
        if (c2 <= t1) PUSH(ra + 8, jb);
        if (c3 <= t1) PUSH(ra + 8, jb + 1);
        if (c4 <= t2) PUSH(ra + 16, jb);
        if (c5 <= t2) PUSH(ra + 16, jb + 1);
        if (c6 <= t3) PUSH(ra + 24, jb);
        if (c7 <= t3) PUSH(ra + 24, jb + 1);
    }
#undef PUSH

    // ---------------- drain queue: 32 lanes rescore distinct candidates ----------------
    __syncwarp();
    int n = *(volatile int*)(qcnt + wid);
    if (n > QCAP) n = QCAP;
    for (int base = 0; base < n; base += 32) {
        int k2 = base + lane;
        if (k2 < n) exact_commit(que[wid * QCAP + k2], z, cb, blockRow, zzs, eef, minr);
    }
    __syncthreads();

    // ---------------- gather + write both tuple halves ----------------
#pragma unroll
    for (int it = 0; it < 2; ++it) {
        int row = (tid >> 1) + it * 256, hh = tid & 1;
        int j = (int)(unsigned)(minr[row] & 0xFFFFFFFFull);
        size_t g = blockRow + row;
        const float4* s4 = (const float4*)(cb + (size_t)j * Dm + hh * 32);
        float4* o1 = (float4*)(out + g * Dm + hh * 32);
        float4* o2 = (half > 0) ? (float4*)(out + half + g * Dm + hh * 32) : nullptr;
#pragma unroll
        for (int i = 0; i < 8; ++i) {
            float4 tv = s4[i];
            o1[i] = tv;
            if (o2) o2[i] = tv;
        }
    }
}

extern "C" void kernel_launch(void* const* d_in, const int* in_sizes, int n_in,
                              void* d_out, int out_size) {
    const float* z = (const float*)d_in[0];
    const float* cb = (const float*)d_in[1];
    float* out = (float*)d_out;
    const int N = in_sizes[0] / Dm;                      // 131072
    long long half = ((long long)out_size >= 2LL * N * Dm) ? (long long)out_size / 2 : 0;

    cudaFuncSetAttribute(vq_kernel, cudaFuncAttributeMaxDynamicSharedMemorySize, SM_TOTAL);
    prep_kernel<<<2, 256>>>(cb);
    vq_kernel<<<N / ROWS_CTA, THREADS, SM_TOTAL>>>(z, cb, out, half);
}